// round 14
// baseline (speedup 1.0000x reference)
#include <cuda_runtime.h>

typedef unsigned long long u64;

#define S_ 512
#define B_ 64
#define H_ 1024
#define G_ 4096   // 4*H
#define M_ 32768  // S*B
#define NCTA_ 128

// ---------------- scratch (__device__ globals; allocation-free rule) --------
__device__ float g_gi[(size_t)S_ * (size_t)B_ * (size_t)G_];   // 512 MB
__device__ float g_y0[(size_t)S_ * (size_t)B_ * (size_t)H_];   // layer-0 h history [t][b][h]
__device__ float g_xT[(size_t)H_ * M_];                        // x transposed [k][m]
__device__ float g_y0T[(size_t)H_ * M_];                       // y0 transposed [k][m] (m = t*64+b)
__device__ float g_wT[2][(size_t)H_ * G_];                     // w_ih transposed [k][n]
__device__ int   g_flag[NCTA_];                                // per-CTA step progress
__device__ unsigned g_barCnt = 0;
__device__ unsigned g_barGen = 0;

// ---------------- packed fp32x2 helpers ----------------
__device__ __forceinline__ u64 pack_dup(float x) {
    u64 r; asm("mov.b64 %0, {%1, %1};" : "=l"(r) : "f"(x)); return r;
}
__device__ __forceinline__ void fma2(u64 &d, u64 a, u64 b) {
    asm("fma.rn.f32x2 %0, %1, %2, %0;" : "+l"(d) : "l"(a), "l"(b));
}
__device__ __forceinline__ float2 unpack2(u64 v) {
    float2 f; asm("mov.b64 {%0, %1}, %2;" : "=f"(f.x), "=f"(f.y) : "l"(v)); return f;
}
__device__ __forceinline__ float hsum2(u64 v) {
    float2 f = unpack2(v); return f.x + f.y;
}
__device__ __forceinline__ float sigf(float x) { return 1.0f / (1.0f + __expf(-x)); }
__device__ __forceinline__ float tanhf_(float x) { return 2.0f / (1.0f + __expf(-2.0f * x)) - 1.0f; }

__device__ __forceinline__ void cpasync16(float* dst_smem, const float* src) {
    unsigned d = (unsigned)__cvta_generic_to_shared(dst_smem);
    asm volatile("cp.async.cg.shared.global [%0], [%1], 16;" :: "r"(d), "l"(src));
}

// Device-wide barrier — used ONCE per lstm launch (orders the flag reset).
__device__ __forceinline__ void gsync() {
    __syncthreads();
    if (threadIdx.x == 0) {
        __threadfence();
        unsigned my = *(volatile unsigned*)&g_barGen;
        if (atomicAdd(&g_barCnt, 1) == NCTA_ - 1) {
            atomicExch(&g_barCnt, 0);
            __threadfence();
            atomicExch(&g_barGen, my + 1);
        } else {
            while (*(volatile unsigned*)&g_barGen == my) __nanosleep(32);
        }
        __threadfence();
    }
    __syncthreads();
}

// ============================================================================
// transp: dst[c*R + r] = src[r*C + c]  (tiled 32x32, block 32x8)
// ============================================================================
__global__ void transp(const float* __restrict__ src, float* __restrict__ dst,
                       int R, int C)
{
    __shared__ float tl[32][33];
    int bx = blockIdx.x * 32;
    int by = blockIdx.y * 32;
    int x = threadIdx.x, y = threadIdx.y;
#pragma unroll
    for (int i = 0; i < 32; i += 8)
        tl[y + i][x] = src[(size_t)(by + y + i) * C + bx + x];
    __syncthreads();
#pragma unroll
    for (int i = 0; i < 32; i += 8)
        dst[(size_t)(bx + y + i) * R + by + x] = tl[x][y + i];
}

// ============================================================================
// gemm3: GI[m,n] = sum_k AT[k,m] WT[k,n] + biases.  All-cp.async operands,
// 4-stage pipeline (prefetch distance 3), 8x8 thread tile, 256 threads, occ 2.
// ============================================================================
#define G3_STAGE_F 4096                       // As 2048 + Bs 2048 floats
#define G3_SMEM    (4 * G3_STAGE_F * 4)       // 65536 B

__global__ __launch_bounds__(256, 2) void gemm3(
    int layer, const float* __restrict__ bih, const float* __restrict__ bhh)
{
    extern __shared__ float g3[];
    const float* AT = layer ? g_y0T : g_xT;
    const float* WT = g_wT[layer];
    float* GI = g_gi;

    int bn = blockIdx.x, bm = blockIdx.y;
    int t = threadIdx.x;
    int tx = t & 15, ty = t >> 4;

    int kr0 = t >> 5, off0 = (t & 31) * 4;
    int kr1 = (t + 256) >> 5, off1 = off0;

    const float* Abase = AT + bm * 128;
    const float* Bbase = WT + bn * 128;

    u64 acc[8][4];
#pragma unroll
    for (int i = 0; i < 8; i++)
#pragma unroll
        for (int j = 0; j < 4; j++) acc[i][j] = 0ull;

    #define G3_ISSUE(kt, s) do {                                               \
        float* As_ = g3 + (s) * G3_STAGE_F;                                    \
        float* Bs_ = As_ + 2048;                                               \
        size_t kb = (size_t)((kt) * 16);                                       \
        cpasync16(As_ + kr0 * 128 + off0, Abase + (kb + kr0) * M_ + off0);     \
        cpasync16(As_ + kr1 * 128 + off1, Abase + (kb + kr1) * M_ + off1);     \
        cpasync16(Bs_ + kr0 * 128 + off0, Bbase + (kb + kr0) * G_ + off0);     \
        cpasync16(Bs_ + kr1 * 128 + off1, Bbase + (kb + kr1) * G_ + off1);     \
        asm volatile("cp.async.commit_group;");                                \
    } while (0)

    G3_ISSUE(0, 0);
    G3_ISSUE(1, 1);
    G3_ISSUE(2, 2);

    int col0 = bn * 128 + tx * 8;
    float bsum[8];
#pragma unroll
    for (int j = 0; j < 8; j++) bsum[j] = bih[col0 + j] + bhh[col0 + j];

#pragma unroll 1
    for (int kt = 0; kt < 64; kt++) {
        if (kt < 62)       asm volatile("cp.async.wait_group 2;" ::: "memory");
        else if (kt == 62) asm volatile("cp.async.wait_group 1;" ::: "memory");
        else               asm volatile("cp.async.wait_group 0;" ::: "memory");
        __syncthreads();
        if (kt + 3 < 64) G3_ISSUE(kt + 3, (kt + 3) & 3);

        const float* As_ = g3 + (kt & 3) * G3_STAGE_F;
        const float* Bs_ = As_ + 2048;
#pragma unroll
        for (int k = 0; k < 16; k++) {
            float4 av0 = *(const float4*)(As_ + k * 128 + ty * 8);
            float4 av1 = *(const float4*)(As_ + k * 128 + ty * 8 + 4);
            const ulonglong2* bp2 = (const ulonglong2*)(Bs_ + k * 128 + tx * 8);
            ulonglong2 bA = bp2[0], bB = bp2[1];
            float a_[8] = {av0.x, av0.y, av0.z, av0.w, av1.x, av1.y, av1.z, av1.w};
#pragma unroll
            for (int i = 0; i < 8; i++) {
                u64 ad = pack_dup(a_[i]);
                fma2(acc[i][0], ad, bA.x);
                fma2(acc[i][1], ad, bA.y);
                fma2(acc[i][2], ad, bB.x);
                fma2(acc[i][3], ad, bB.y);
            }
        }
    }
    #undef G3_ISSUE

    int row0 = bm * 128 + ty * 8;
#pragma unroll
    for (int i = 0; i < 8; i++) {
#pragma unroll
        for (int jp = 0; jp < 4; jp++) {
            float2 v = unpack2(acc[i][jp]);
            GI[(size_t)(row0 + i) * G_ + col0 + jp * 2]     = v.x + bsum[jp * 2];
            GI[(size_t)(row0 + i) * G_ + col0 + jp * 2 + 1] = v.y + bsum[jp * 2 + 1];
        }
    }
}

// ---------------- 4x4 register-tile inner kernel ----------
struct Ops {
    ulonglong2 w0, w1, w2, w3;
    ulonglong2 h0, h1, h2, h3;
};
// h stage with row stride 12 (8k sub-chunks)
__device__ __forceinline__ void load_ops12(Ops &o, const float* wp, const float* hp) {
    o.w0 = *(const ulonglong2*)(wp + 0);
    o.w1 = *(const ulonglong2*)(wp + 32);
    o.w2 = *(const ulonglong2*)(wp + 64);
    o.w3 = *(const ulonglong2*)(wp + 96);
    o.h0 = *(const ulonglong2*)(hp + 0 * 12);
    o.h1 = *(const ulonglong2*)(hp + 4 * 12);
    o.h2 = *(const ulonglong2*)(hp + 8 * 12);
    o.h3 = *(const ulonglong2*)(hp + 12 * 12);
}
__device__ __forceinline__ void do_fma(u64 (&acc)[4][4], const Ops &o) {
    fma2(acc[0][0], o.w0.x, o.h0.x); fma2(acc[0][0], o.w0.y, o.h0.y);
    fma2(acc[1][0], o.w1.x, o.h0.x); fma2(acc[1][0], o.w1.y, o.h0.y);
    fma2(acc[2][0], o.w2.x, o.h0.x); fma2(acc[2][0], o.w2.y, o.h0.y);
    fma2(acc[3][0], o.w3.x, o.h0.x); fma2(acc[3][0], o.w3.y, o.h0.y);
    fma2(acc[0][1], o.w0.x, o.h1.x); fma2(acc[0][1], o.w0.y, o.h1.y);
    fma2(acc[1][1], o.w1.x, o.h1.x); fma2(acc[1][1], o.w1.y, o.h1.y);
    fma2(acc[2][1], o.w2.x, o.h1.x); fma2(acc[2][1], o.w2.y, o.h1.y);
    fma2(acc[3][1], o.w3.x, o.h1.x); fma2(acc[3][1], o.w3.y, o.h1.y);
    fma2(acc[0][2], o.w0.x, o.h2.x); fma2(acc[0][2], o.w0.y, o.h2.y);
    fma2(acc[1][2], o.w1.x, o.h2.x); fma2(acc[1][2], o.w1.y, o.h2.y);
    fma2(acc[2][2], o.w2.x, o.h2.x); fma2(acc[2][2], o.w2.y, o.h2.y);
    fma2(acc[3][2], o.w3.x, o.h2.x); fma2(acc[3][2], o.w3.y, o.h2.y);
    fma2(acc[0][3], o.w0.x, o.h3.x); fma2(acc[0][3], o.w0.y, o.h3.y);
    fma2(acc[1][3], o.w1.x, o.h3.x); fma2(acc[1][3], o.w1.y, o.h3.y);
    fma2(acc[2][3], o.w2.x, o.h3.x); fma2(acc[2][3], o.w2.y, o.h3.y);
    fma2(acc[3][3], o.w3.x, o.h3.x); fma2(acc[3][3], o.w3.y, o.h3.y);
}

// ============================================================================
// Persistent recurrent layer (round-10/13 winner) with a DEEPER h pipeline:
// 8k sub-chunks x 4 stages (prefetch distance 3). Same smem footprint.
// ============================================================================
#define WSM_F   (256 * 32 * 4)
#define HSTG_F  (16 * 12)               // 16 rows x stride 12 (8 k + pad)
#define HBUF_F  (16 * 4 * HSTG_F)       // 16 warps x 4 stages
#define CMB_F   (4 * 64 * 36)
#define SMEM_STEP ((WSM_F + HBUF_F + CMB_F) * 4)

__global__ __launch_bounds__(512, 1) void lstm_layer(
    int layer, const float* __restrict__ whh,
    float* __restrict__ y1, float* __restrict__ hn_base, float* __restrict__ cn_base)
{
    extern __shared__ float sm[];
    float* Wsm  = sm;
    float* Hbuf = sm + WSM_F;
    float* Cmb  = sm + WSM_F + HBUF_F;

    const size_t BH = (size_t)B_ * H_;
    int tid  = threadIdx.x;
    int lane = tid & 31;
    int wy   = tid >> 5;
    int ks   = wy & 3;
    int wb0  = (wy >> 2) * 16;
    int lx   = lane & 3;
    int ly   = lane >> 2;
    int jb   = blockIdx.x * 8;

    float* hbase_ = (layer == 0) ? g_y0 : y1;

    {
        int c = tid & 31;
        int wn = ((c >> 3) * H_) + jb + (c & 7);
        const float* wrow = whh + (size_t)wn * H_;
        int dstbase = (c & 3) * 32 + (c >> 2) * 4;
        int k4b = tid >> 5;
#pragma unroll
        for (int q = 0; q < 16; q++) {
            int k4 = k4b + q * 16;
            float4 v = *(const float4*)(wrow + k4 * 4);
            *(float4*)&Wsm[k4 * 128 + dstbase] = v;
        }
    }
    if (tid == 0) ((volatile int*)g_flag)[blockIdx.x] = 0;
    gsync();

    float* hwbuf = Hbuf + wy * (4 * HSTG_F);
    int n_base = ((ly >> 1) * H_) + jb + ((ly & 1) * 4);
    int cb = tid >> 3, cj = tid & 7;
    float cst = 0.0f;
    const volatile int* myflag = (volatile int*)&g_flag[ks * 32 + lane];
    int lrow = lane >> 1, lkq = lane & 1;   // h loader: 1 cpasync16 per lane

    for (int t = 0; t < S_; t++) {
        const float* gi_t = g_gi + (size_t)t * B_ * G_;
        float4 gi4[4];
        if (ks == 0) {
#pragma unroll
            for (int rr = 0; rr < 4; rr++)
                gi4[rr] = *(const float4*)(gi_t + (size_t)(wb0 + lx + 4 * rr) * G_ + n_base);
        }

        u64 acc[4][4];
#pragma unroll
        for (int cc = 0; cc < 4; cc++)
#pragma unroll
            for (int rr = 0; rr < 4; rr++) acc[cc][rr] = 0ull;

        if (t > 0) {
            for (;;) {
                int v = *myflag;
                if (__all_sync(0xffffffffu, v >= t)) break;
                __nanosleep(64);
            }
            __threadfence();

            const float* hsrc = hbase_ + (size_t)(t - 1) * BH;
            const float* hk = hsrc + ks * 256;
            const float* hrow = hk + (size_t)(wb0 + lrow) * H_ + lkq * 4;

            // prologue: sub-chunks 0..2
#pragma unroll
            for (int p = 0; p < 3; p++) {
                cpasync16(hwbuf + p * HSTG_F + lrow * 12 + lkq * 4, hrow + p * 8);
                asm volatile("cp.async.commit_group;");
            }

#pragma unroll 2
            for (int ch = 0; ch < 32; ch++) {
                if (ch < 30)       asm volatile("cp.async.wait_group 2;" ::: "memory");
                else if (ch == 30) asm volatile("cp.async.wait_group 1;" ::: "memory");
                else               asm volatile("cp.async.wait_group 0;" ::: "memory");
                __syncwarp();

                if (ch + 3 < 32) {
                    cpasync16(hwbuf + ((ch + 3) & 3) * HSTG_F + lrow * 12 + lkq * 4,
                              hrow + (ch + 3) * 8);
                    asm volatile("cp.async.commit_group;");
                }

                const float* hs = hwbuf + (ch & 3) * HSTG_F;
                int k4g0 = ks * 64 + ch * 2;
                const float* wbase = Wsm + (size_t)k4g0 * 128 + ly * 4;
                const float* hb = hs + lx * 12;

                Ops o0, o1;
                load_ops12(o0, wbase, hb);
                load_ops12(o1, wbase + 128, hb + 4);
                do_fma(acc, o0);
                do_fma(acc, o1);
                __syncwarp();
            }
        }

#pragma unroll
        for (int rr = 0; rr < 4; rr++) {
            float4 v;
            v.x = hsum2(acc[0][rr]);
            v.y = hsum2(acc[1][rr]);
            v.z = hsum2(acc[2][rr]);
            v.w = hsum2(acc[3][rr]);
            if (ks == 0) {
                v.x += gi4[rr].x; v.y += gi4[rr].y;
                v.z += gi4[rr].z; v.w += gi4[rr].w;
            }
            int b = wb0 + lx + 4 * rr;
            *(float4*)&Cmb[(ks * 64 + b) * 36 + ly * 4] = v;
        }
        __syncthreads();

        float z[4];
#pragma unroll
        for (int g = 0; g < 4; g++) {
            int c = g * 8 + cj;
            z[g] = Cmb[(0 * 64 + cb) * 36 + c]
                 + Cmb[(1 * 64 + cb) * 36 + c]
                 + Cmb[(2 * 64 + cb) * 36 + c]
                 + Cmb[(3 * 64 + cb) * 36 + c];
        }
        cst = sigf(z[1]) * cst + sigf(z[0]) * tanhf_(z[2]);
        float hv = sigf(z[3]) * tanhf_(cst);

        size_t hoff = (size_t)cb * H_ + jb + cj;
        (hbase_ + (size_t)t * BH)[hoff] = hv;
        if (layer == 0)
            g_y0T[(size_t)(jb + cj) * M_ + t * 64 + cb] = hv;
        if (t == S_ - 1) {
            size_t o = (size_t)layer * BH + hoff;
            hn_base[o] = hv;
            cn_base[o] = cst;
        }

        __syncthreads();
        if (tid == 0) {
            __threadfence();
            atomicExch(&g_flag[blockIdx.x], t + 1);
        }
        __syncthreads();
    }
}

// ============================================================================
// kernel_launch: 7 graph nodes.
// Output layout: y1 [S,B,H] | h_n [2,B,H] | c_n [2,B,H]
// ============================================================================
extern "C" void kernel_launch(void* const* d_in, const int* in_sizes, int n_in,
                              void* d_out, int out_size)
{
    const float* x     = (const float*)d_in[0];
    const float* w_ih0 = (const float*)d_in[1];
    const float* w_hh0 = (const float*)d_in[2];
    const float* b_ih0 = (const float*)d_in[3];
    const float* b_hh0 = (const float*)d_in[4];
    const float* w_ih1 = (const float*)d_in[5];
    const float* w_hh1 = (const float*)d_in[6];
    const float* b_ih1 = (const float*)d_in[7];
    const float* b_hh1 = (const float*)d_in[8];

    float* y1 = (float*)d_out;
    float* hn = y1 + (size_t)S_ * B_ * H_;
    float* cn = hn + 2 * (size_t)B_ * H_;

    cudaFuncSetAttribute(lstm_layer, cudaFuncAttributeMaxDynamicSharedMemorySize, SMEM_STEP);
    cudaFuncSetAttribute(gemm3, cudaFuncAttributeMaxDynamicSharedMemorySize, G3_SMEM);

    float* xT  = nullptr; cudaGetSymbolAddress((void**)&xT,  g_xT);
    float* wT  = nullptr; cudaGetSymbolAddress((void**)&wT,  g_wT);

    dim3 tb(32, 8);
    transp<<<dim3(H_ / 32, M_ / 32), tb>>>(x, xT, M_, H_);
    transp<<<dim3(H_ / 32, G_ / 32), tb>>>(w_ih0, wT, G_, H_);
    transp<<<dim3(H_ / 32, G_ / 32), tb>>>(w_ih1, wT + (size_t)H_ * G_, G_, H_);

    dim3 ggrid(G_ / 128, M_ / 128);  // (32, 256)

    gemm3<<<ggrid, 256, G3_SMEM>>>(0, b_ih0, b_hh0);
    lstm_layer<<<NCTA_, 512, SMEM_STEP>>>(0, w_hh0, y1, hn, cn);
    gemm3<<<ggrid, 256, G3_SMEM>>>(1, b_ih1, b_hh1);
    lstm_layer<<<NCTA_, 512, SMEM_STEP>>>(1, w_hh1, y1, hn, cn);
}

// round 16
// speedup vs baseline: 1.0007x; 1.0007x over previous
#include <cuda_runtime.h>

typedef unsigned long long u64;

#define S_ 512
#define B_ 64
#define H_ 1024
#define G_ 4096   // 4*H
#define M_ 32768  // S*B
#define NCTA_ 128

// ---------------- scratch (__device__ globals; allocation-free rule) --------
__device__ float g_gi[(size_t)S_ * (size_t)B_ * (size_t)G_];   // 512 MB
__device__ float g_y0[(size_t)S_ * (size_t)B_ * (size_t)H_];   // layer-0 h history [t][b][h]
__device__ float g_xT[(size_t)H_ * M_];                        // x transposed [k][m]
__device__ float g_y0T[(size_t)H_ * M_];                       // y0 transposed [k][m] (m = t*64+b)
__device__ float g_wT[2][(size_t)H_ * G_];                     // w_ih transposed [k][n]
__device__ int   g_flag[NCTA_];                                // per-CTA step progress
__device__ unsigned g_barCnt = 0;
__device__ unsigned g_barGen = 0;

// ---------------- packed fp32x2 helpers ----------------
__device__ __forceinline__ u64 pack_dup(float x) {
    u64 r; asm("mov.b64 %0, {%1, %1};" : "=l"(r) : "f"(x)); return r;
}
__device__ __forceinline__ void fma2(u64 &d, u64 a, u64 b) {
    asm("fma.rn.f32x2 %0, %1, %2, %0;" : "+l"(d) : "l"(a), "l"(b));
}
__device__ __forceinline__ float2 unpack2(u64 v) {
    float2 f; asm("mov.b64 {%0, %1}, %2;" : "=f"(f.x), "=f"(f.y) : "l"(v)); return f;
}
__device__ __forceinline__ float hsum2(u64 v) {
    float2 f = unpack2(v); return f.x + f.y;
}
__device__ __forceinline__ float sigf(float x) { return 1.0f / (1.0f + __expf(-x)); }
__device__ __forceinline__ float tanhf_(float x) { return 2.0f / (1.0f + __expf(-2.0f * x)) - 1.0f; }

__device__ __forceinline__ void cpasync16(float* dst_smem, const float* src) {
    unsigned d = (unsigned)__cvta_generic_to_shared(dst_smem);
    asm volatile("cp.async.cg.shared.global [%0], [%1], 16;" :: "r"(d), "l"(src));
}

// Device-wide barrier — used ONCE per lstm launch (orders the flag reset).
__device__ __forceinline__ void gsync() {
    __syncthreads();
    if (threadIdx.x == 0) {
        __threadfence();
        unsigned my = *(volatile unsigned*)&g_barGen;
        if (atomicAdd(&g_barCnt, 1) == NCTA_ - 1) {
            atomicExch(&g_barCnt, 0);
            __threadfence();
            atomicExch(&g_barGen, my + 1);
        } else {
            while (*(volatile unsigned*)&g_barGen == my) __nanosleep(32);
        }
        __threadfence();
    }
    __syncthreads();
}

// ============================================================================
// transp: dst[c*R + r] = src[r*C + c]  (tiled 32x32, block 32x8)
// ============================================================================
__global__ void transp(const float* __restrict__ src, float* __restrict__ dst,
                       int R, int C)
{
    __shared__ float tl[32][33];
    int bx = blockIdx.x * 32;
    int by = blockIdx.y * 32;
    int x = threadIdx.x, y = threadIdx.y;
#pragma unroll
    for (int i = 0; i < 32; i += 8)
        tl[y + i][x] = src[(size_t)(by + y + i) * C + bx + x];
    __syncthreads();
#pragma unroll
    for (int i = 0; i < 32; i += 8)
        dst[(size_t)(bx + y + i) * R + by + x] = tl[x][y + i];
}

// ============================================================================
// gemm3: GI[m,n] = sum_k AT[k,m] WT[k,n] + biases.  All-cp.async operands,
// 4-stage pipeline (prefetch distance 3), 8x8 thread tile, 256 threads, occ 2.
// ============================================================================
#define G3_STAGE_F 4096                       // As 2048 + Bs 2048 floats
#define G3_SMEM    (4 * G3_STAGE_F * 4)       // 65536 B

__global__ __launch_bounds__(256, 2) void gemm3(
    int layer, const float* __restrict__ bih, const float* __restrict__ bhh)
{
    extern __shared__ float g3[];
    const float* AT = layer ? g_y0T : g_xT;
    const float* WT = g_wT[layer];
    float* GI = g_gi;

    int bn = blockIdx.x, bm = blockIdx.y;
    int t = threadIdx.x;
    int tx = t & 15, ty = t >> 4;

    int kr0 = t >> 5, off0 = (t & 31) * 4;
    int kr1 = (t + 256) >> 5, off1 = off0;

    const float* Abase = AT + bm * 128;
    const float* Bbase = WT + bn * 128;

    u64 acc[8][4];
#pragma unroll
    for (int i = 0; i < 8; i++)
#pragma unroll
        for (int j = 0; j < 4; j++) acc[i][j] = 0ull;

    #define G3_ISSUE(kt, s) do {                                               \
        float* As_ = g3 + (s) * G3_STAGE_F;                                    \
        float* Bs_ = As_ + 2048;                                               \
        size_t kb = (size_t)((kt) * 16);                                       \
        cpasync16(As_ + kr0 * 128 + off0, Abase + (kb + kr0) * M_ + off0);     \
        cpasync16(As_ + kr1 * 128 + off1, Abase + (kb + kr1) * M_ + off1);     \
        cpasync16(Bs_ + kr0 * 128 + off0, Bbase + (kb + kr0) * G_ + off0);     \
        cpasync16(Bs_ + kr1 * 128 + off1, Bbase + (kb + kr1) * G_ + off1);     \
        asm volatile("cp.async.commit_group;");                                \
    } while (0)

    G3_ISSUE(0, 0);
    G3_ISSUE(1, 1);
    G3_ISSUE(2, 2);

    int col0 = bn * 128 + tx * 8;
    float bsum[8];
#pragma unroll
    for (int j = 0; j < 8; j++) bsum[j] = bih[col0 + j] + bhh[col0 + j];

#pragma unroll 1
    for (int kt = 0; kt < 64; kt++) {
        if (kt < 62)       asm volatile("cp.async.wait_group 2;" ::: "memory");
        else if (kt == 62) asm volatile("cp.async.wait_group 1;" ::: "memory");
        else               asm volatile("cp.async.wait_group 0;" ::: "memory");
        __syncthreads();
        if (kt + 3 < 64) G3_ISSUE(kt + 3, (kt + 3) & 3);

        const float* As_ = g3 + (kt & 3) * G3_STAGE_F;
        const float* Bs_ = As_ + 2048;
#pragma unroll
        for (int k = 0; k < 16; k++) {
            float4 av0 = *(const float4*)(As_ + k * 128 + ty * 8);
            float4 av1 = *(const float4*)(As_ + k * 128 + ty * 8 + 4);
            const ulonglong2* bp2 = (const ulonglong2*)(Bs_ + k * 128 + tx * 8);
            ulonglong2 bA = bp2[0], bB = bp2[1];
            float a_[8] = {av0.x, av0.y, av0.z, av0.w, av1.x, av1.y, av1.z, av1.w};
#pragma unroll
            for (int i = 0; i < 8; i++) {
                u64 ad = pack_dup(a_[i]);
                fma2(acc[i][0], ad, bA.x);
                fma2(acc[i][1], ad, bA.y);
                fma2(acc[i][2], ad, bB.x);
                fma2(acc[i][3], ad, bB.y);
            }
        }
    }
    #undef G3_ISSUE

    int row0 = bm * 128 + ty * 8;
#pragma unroll
    for (int i = 0; i < 8; i++) {
#pragma unroll
        for (int jp = 0; jp < 4; jp++) {
            float2 v = unpack2(acc[i][jp]);
            GI[(size_t)(row0 + i) * G_ + col0 + jp * 2]     = v.x + bsum[jp * 2];
            GI[(size_t)(row0 + i) * G_ + col0 + jp * 2 + 1] = v.y + bsum[jp * 2 + 1];
        }
    }
}

// ---------------- 4x4 register-tile inner kernel (h stage stride 20) --------
struct Ops {
    ulonglong2 w0, w1, w2, w3;
    ulonglong2 h0, h1, h2, h3;
};
__device__ __forceinline__ void load_ops(Ops &o, const float* wp, const float* hp) {
    o.w0 = *(const ulonglong2*)(wp + 0);
    o.w1 = *(const ulonglong2*)(wp + 32);
    o.w2 = *(const ulonglong2*)(wp + 64);
    o.w3 = *(const ulonglong2*)(wp + 96);
    o.h0 = *(const ulonglong2*)(hp + 0 * 20);
    o.h1 = *(const ulonglong2*)(hp + 4 * 20);
    o.h2 = *(const ulonglong2*)(hp + 8 * 20);
    o.h3 = *(const ulonglong2*)(hp + 12 * 20);
}
__device__ __forceinline__ void do_fma(u64 (&acc)[4][4], const Ops &o) {
    fma2(acc[0][0], o.w0.x, o.h0.x); fma2(acc[0][0], o.w0.y, o.h0.y);
    fma2(acc[1][0], o.w1.x, o.h0.x); fma2(acc[1][0], o.w1.y, o.h0.y);
    fma2(acc[2][0], o.w2.x, o.h0.x); fma2(acc[2][0], o.w2.y, o.h0.y);
    fma2(acc[3][0], o.w3.x, o.h0.x); fma2(acc[3][0], o.w3.y, o.h0.y);
    fma2(acc[0][1], o.w0.x, o.h1.x); fma2(acc[0][1], o.w0.y, o.h1.y);
    fma2(acc[1][1], o.w1.x, o.h1.x); fma2(acc[1][1], o.w1.y, o.h1.y);
    fma2(acc[2][1], o.w2.x, o.h1.x); fma2(acc[2][1], o.w2.y, o.h1.y);
    fma2(acc[3][1], o.w3.x, o.h1.x); fma2(acc[3][1], o.w3.y, o.h1.y);
    fma2(acc[0][2], o.w0.x, o.h2.x); fma2(acc[0][2], o.w0.y, o.h2.y);
    fma2(acc[1][2], o.w1.x, o.h2.x); fma2(acc[1][2], o.w1.y, o.h2.y);
    fma2(acc[2][2], o.w2.x, o.h2.x); fma2(acc[2][2], o.w2.y, o.h2.y);
    fma2(acc[3][2], o.w3.x, o.h2.x); fma2(acc[3][2], o.w3.y, o.h2.y);
    fma2(acc[0][3], o.w0.x, o.h3.x); fma2(acc[0][3], o.w0.y, o.h3.y);
    fma2(acc[1][3], o.w1.x, o.h3.x); fma2(acc[1][3], o.w1.y, o.h3.y);
    fma2(acc[2][3], o.w2.x, o.h3.x); fma2(acc[2][3], o.w2.y, o.h3.y);
    fma2(acc[3][3], o.w3.x, o.h3.x); fma2(acc[3][3], o.w3.y, o.h3.y);
}

// ============================================================================
// Persistent recurrent layer — round-13 winner with h pipeline 2 -> 3 stages.
// Stage row stride 20 (16 data + 4 pad) so 3 stages fit the 227KB smem cap:
// (32768 + 16*3*320 + 9216)*4 = 229376 B.
// ============================================================================
#define WSM_F   (256 * 32 * 4)
#define HSTG_F  (16 * 20)                // 16 rows x stride 20
#define HBUF_F  (16 * 3 * HSTG_F)        // 16 warps x 3 stages
#define CMB_F   (4 * 64 * 36)
#define SMEM_STEP ((WSM_F + HBUF_F + CMB_F) * 4)

__global__ __launch_bounds__(512, 1) void lstm_layer(
    int layer, const float* __restrict__ whh,
    float* __restrict__ y1, float* __restrict__ hn_base, float* __restrict__ cn_base)
{
    extern __shared__ float sm[];
    float* Wsm  = sm;
    float* Hbuf = sm + WSM_F;
    float* Cmb  = sm + WSM_F + HBUF_F;

    const size_t BH = (size_t)B_ * H_;
    int tid  = threadIdx.x;
    int lane = tid & 31;
    int wy   = tid >> 5;
    int ks   = wy & 3;
    int wb0  = (wy >> 2) * 16;
    int lx   = lane & 3;
    int ly   = lane >> 2;
    int jb   = blockIdx.x * 8;

    float* hbase_ = (layer == 0) ? g_y0 : y1;

    {
        int c = tid & 31;
        int wn = ((c >> 3) * H_) + jb + (c & 7);
        const float* wrow = whh + (size_t)wn * H_;
        int dstbase = (c & 3) * 32 + (c >> 2) * 4;
        int k4b = tid >> 5;
#pragma unroll
        for (int q = 0; q < 16; q++) {
            int k4 = k4b + q * 16;
            float4 v = *(const float4*)(wrow + k4 * 4);
            *(float4*)&Wsm[k4 * 128 + dstbase] = v;
        }
    }
    if (tid == 0) ((volatile int*)g_flag)[blockIdx.x] = 0;
    gsync();

    float* hwbuf = Hbuf + wy * (3 * HSTG_F);
    int n_base = ((ly >> 1) * H_) + jb + ((ly & 1) * 4);
    int cb = tid >> 3, cj = tid & 7;
    float cst = 0.0f;
    const volatile int* myflag = (volatile int*)&g_flag[ks * 32 + lane];

    for (int t = 0; t < S_; t++) {
        const float* gi_t = g_gi + (size_t)t * B_ * G_;
        float4 gi4[4];
        if (ks == 0) {
#pragma unroll
            for (int rr = 0; rr < 4; rr++)
                gi4[rr] = *(const float4*)(gi_t + (size_t)(wb0 + lx + 4 * rr) * G_ + n_base);
        }

        u64 acc[4][4];
#pragma unroll
        for (int cc = 0; cc < 4; cc++)
#pragma unroll
            for (int rr = 0; rr < 4; rr++) acc[cc][rr] = 0ull;

        if (t > 0) {
            for (;;) {
                int v = *myflag;
                if (__all_sync(0xffffffffu, v >= t)) break;
                __nanosleep(64);
            }
            __threadfence();

            const float* hsrc = hbase_ + (size_t)(t - 1) * BH;
            const float* hk = hsrc + ks * 256;

            // prologue: chunks 0 and 1 into stages 0, 1
#pragma unroll
            for (int p = 0; p < 2; p++) {
#pragma unroll
                for (int q = 0; q < 2; q++) {
                    int li = lane + 32 * q;
                    int rowb = li & 15, kq = li >> 4;
                    cpasync16(hwbuf + p * HSTG_F + rowb * 20 + kq * 4,
                              hk + (size_t)p * 16 + (size_t)(wb0 + rowb) * H_ + kq * 4);
                }
                asm volatile("cp.async.commit_group;");
            }

            for (int ch = 0; ch < 16; ch++) {
                if (ch < 14) {
                    // issue chunk ch+2 into stage (ch+2)%3
                    float* dst = hwbuf + ((ch + 2) % 3) * HSTG_F;
                    const float* src = hk + (ch + 2) * 16;
#pragma unroll
                    for (int q = 0; q < 2; q++) {
                        int li = lane + 32 * q;
                        int rowb = li & 15, kq = li >> 4;
                        cpasync16(dst + rowb * 20 + kq * 4,
                                  src + (size_t)(wb0 + rowb) * H_ + kq * 4);
                    }
                    asm volatile("cp.async.commit_group;");
                    asm volatile("cp.async.wait_group 2;");
                } else if (ch == 14) {
                    asm volatile("cp.async.wait_group 1;");
                } else {
                    asm volatile("cp.async.wait_group 0;");
                }
                __syncwarp();

                const float* hs = hwbuf + (ch % 3) * HSTG_F;
                int k4g0 = ks * 64 + ch * 4;
                const float* wbase = Wsm + (size_t)k4g0 * 128 + ly * 4;
                const float* hb = hs + lx * 20;

                Ops ops0, ops1;
                load_ops(ops0, wbase, hb);
                load_ops(ops1, wbase + 128, hb + 4);
                do_fma(acc, ops0);
                load_ops(ops0, wbase + 256, hb + 8);
                do_fma(acc, ops1);
                load_ops(ops1, wbase + 384, hb + 12);
                do_fma(acc, ops0);
                do_fma(acc, ops1);

                __syncwarp();
            }
        }

#pragma unroll
        for (int rr = 0; rr < 4; rr++) {
            float4 v;
            v.x = hsum2(acc[0][rr]);
            v.y = hsum2(acc[1][rr]);
            v.z = hsum2(acc[2][rr]);
            v.w = hsum2(acc[3][rr]);
            if (ks == 0) {
                v.x += gi4[rr].x; v.y += gi4[rr].y;
                v.z += gi4[rr].z; v.w += gi4[rr].w;
            }
            int b = wb0 + lx + 4 * rr;
            *(float4*)&Cmb[(ks * 64 + b) * 36 + ly * 4] = v;
        }
        __syncthreads();

        float z[4];
#pragma unroll
        for (int g = 0; g < 4; g++) {
            int c = g * 8 + cj;
            z[g] = Cmb[(0 * 64 + cb) * 36 + c]
                 + Cmb[(1 * 64 + cb) * 36 + c]
                 + Cmb[(2 * 64 + cb) * 36 + c]
                 + Cmb[(3 * 64 + cb) * 36 + c];
        }
        cst = sigf(z[1]) * cst + sigf(z[0]) * tanhf_(z[2]);
        float hv = sigf(z[3]) * tanhf_(cst);

        size_t hoff = (size_t)cb * H_ + jb + cj;
        (hbase_ + (size_t)t * BH)[hoff] = hv;
        if (layer == 0)
            g_y0T[(size_t)(jb + cj) * M_ + t * 64 + cb] = hv;
        if (t == S_ - 1) {
            size_t o = (size_t)layer * BH + hoff;
            hn_base[o] = hv;
            cn_base[o] = cst;
        }

        __syncthreads();
        if (tid == 0) {
            __threadfence();
            atomicExch(&g_flag[blockIdx.x], t + 1);
        }
        __syncthreads();
    }
}

// ============================================================================
// kernel_launch: 7 graph nodes.
// Output layout: y1 [S,B,H] | h_n [2,B,H] | c_n [2,B,H]
// ============================================================================
extern "C" void kernel_launch(void* const* d_in, const int* in_sizes, int n_in,
                              void* d_out, int out_size)
{
    const float* x     = (const float*)d_in[0];
    const float* w_ih0 = (const float*)d_in[1];
    const float* w_hh0 = (const float*)d_in[2];
    const float* b_ih0 = (const float*)d_in[3];
    const float* b_hh0 = (const float*)d_in[4];
    const float* w_ih1 = (const float*)d_in[5];
    const float* w_hh1 = (const float*)d_in[6];
    const float* b_ih1 = (const float*)d_in[7];
    const float* b_hh1 = (const float*)d_in[8];

    float* y1 = (float*)d_out;
    float* hn = y1 + (size_t)S_ * B_ * H_;
    float* cn = hn + 2 * (size_t)B_ * H_;

    cudaFuncSetAttribute(lstm_layer, cudaFuncAttributeMaxDynamicSharedMemorySize, SMEM_STEP);
    cudaFuncSetAttribute(gemm3, cudaFuncAttributeMaxDynamicSharedMemorySize, G3_SMEM);

    float* xT  = nullptr; cudaGetSymbolAddress((void**)&xT,  g_xT);
    float* wT  = nullptr; cudaGetSymbolAddress((void**)&wT,  g_wT);

    dim3 tb(32, 8);
    transp<<<dim3(H_ / 32, M_ / 32), tb>>>(x, xT, M_, H_);
    transp<<<dim3(H_ / 32, G_ / 32), tb>>>(w_ih0, wT, G_, H_);
    transp<<<dim3(H_ / 32, G_ / 32), tb>>>(w_ih1, wT + (size_t)H_ * G_, G_, H_);

    dim3 ggrid(G_ / 128, M_ / 128);  // (32, 256)

    gemm3<<<ggrid, 256, G3_SMEM>>>(0, b_ih0, b_hh0);
    lstm_layer<<<NCTA_, 512, SMEM_STEP>>>(0, w_hh0, y1, hn, cn);
    gemm3<<<ggrid, 256, G3_SMEM>>>(1, b_ih1, b_hh1);
    lstm_layer<<<NCTA_, 512, SMEM_STEP>>>(1, w_hh1, y1, hn, cn);
}

// round 17
// speedup vs baseline: 1.0566x; 1.0558x over previous
#include <cuda_runtime.h>

typedef unsigned long long u64;

#define S_ 512
#define B_ 64
#define H_ 1024
#define G_ 4096   // 4*H
#define M_ 32768  // S*B
#define NCTA_ 128

// ---------------- scratch (__device__ globals; allocation-free rule) --------
__device__ float g_gi[(size_t)S_ * (size_t)B_ * (size_t)G_];   // 512 MB
__device__ float g_y0[(size_t)S_ * (size_t)B_ * (size_t)H_];   // layer-0 h history [t][b][h]
__device__ float g_xT[(size_t)H_ * M_];                        // x transposed [k][m]
__device__ float g_y0T[(size_t)H_ * M_];                       // y0 transposed [k][m] (m = t*64+b)
__device__ float g_wT[2][(size_t)H_ * G_];                     // w_ih transposed [k][n]
__device__ int   g_flag[NCTA_];                                // per-CTA step progress
__device__ unsigned g_barCnt = 0;
__device__ unsigned g_barGen = 0;

// ---------------- packed fp32x2 helpers ----------------
__device__ __forceinline__ u64 pack_dup(float x) {
    u64 r; asm("mov.b64 %0, {%1, %1};" : "=l"(r) : "f"(x)); return r;
}
__device__ __forceinline__ void fma2(u64 &d, u64 a, u64 b) {
    asm("fma.rn.f32x2 %0, %1, %2, %0;" : "+l"(d) : "l"(a), "l"(b));
}
__device__ __forceinline__ float2 unpack2(u64 v) {
    float2 f; asm("mov.b64 {%0, %1}, %2;" : "=f"(f.x), "=f"(f.y) : "l"(v)); return f;
}
__device__ __forceinline__ float hsum2(u64 v) {
    float2 f = unpack2(v); return f.x + f.y;
}
__device__ __forceinline__ float sigf(float x) { return 1.0f / (1.0f + __expf(-x)); }
__device__ __forceinline__ float tanhf_(float x) { return 2.0f / (1.0f + __expf(-2.0f * x)) - 1.0f; }

__device__ __forceinline__ void cpasync16(float* dst_smem, const float* src) {
    unsigned d = (unsigned)__cvta_generic_to_shared(dst_smem);
    asm volatile("cp.async.cg.shared.global [%0], [%1], 16;" :: "r"(d), "l"(src));
}

// Device-wide barrier — used ONCE per lstm launch (orders the flag reset).
__device__ __forceinline__ void gsync() {
    __syncthreads();
    if (threadIdx.x == 0) {
        __threadfence();
        unsigned my = *(volatile unsigned*)&g_barGen;
        if (atomicAdd(&g_barCnt, 1) == NCTA_ - 1) {
            atomicExch(&g_barCnt, 0);
            __threadfence();
            atomicExch(&g_barGen, my + 1);
        } else {
            while (*(volatile unsigned*)&g_barGen == my) __nanosleep(32);
        }
        __threadfence();
    }
    __syncthreads();
}

// ============================================================================
// transp: dst[c*R + r] = src[r*C + c]  (tiled 32x32, block 32x8)
// ============================================================================
__global__ void transp(const float* __restrict__ src, float* __restrict__ dst,
                       int R, int C)
{
    __shared__ float tl[32][33];
    int bx = blockIdx.x * 32;
    int by = blockIdx.y * 32;
    int x = threadIdx.x, y = threadIdx.y;
#pragma unroll
    for (int i = 0; i < 32; i += 8)
        tl[y + i][x] = src[(size_t)(by + y + i) * C + bx + x];
    __syncthreads();
#pragma unroll
    for (int i = 0; i < 32; i += 8)
        dst[(size_t)(bx + y + i) * R + by + x] = tl[x][y + i];
}

// ============================================================================
// gemm3: GI[m,n] = sum_k AT[k,m] WT[k,n] + biases.  All-cp.async operands,
// 4-stage pipeline (prefetch distance 3), 8x8 thread tile, 256 threads, occ 2.
// ============================================================================
#define G3_STAGE_F 4096                       // As 2048 + Bs 2048 floats
#define G3_SMEM    (4 * G3_STAGE_F * 4)       // 65536 B

__global__ __launch_bounds__(256, 2) void gemm3(
    int layer, const float* __restrict__ bih, const float* __restrict__ bhh)
{
    extern __shared__ float g3[];
    const float* AT = layer ? g_y0T : g_xT;
    const float* WT = g_wT[layer];
    float* GI = g_gi;

    int bn = blockIdx.x, bm = blockIdx.y;
    int t = threadIdx.x;
    int tx = t & 15, ty = t >> 4;

    int kr0 = t >> 5, off0 = (t & 31) * 4;
    int kr1 = (t + 256) >> 5, off1 = off0;

    const float* Abase = AT + bm * 128;
    const float* Bbase = WT + bn * 128;

    u64 acc[8][4];
#pragma unroll
    for (int i = 0; i < 8; i++)
#pragma unroll
        for (int j = 0; j < 4; j++) acc[i][j] = 0ull;

    #define G3_ISSUE(kt, s) do {                                               \
        float* As_ = g3 + (s) * G3_STAGE_F;                                    \
        float* Bs_ = As_ + 2048;                                               \
        size_t kb = (size_t)((kt) * 16);                                       \
        cpasync16(As_ + kr0 * 128 + off0, Abase + (kb + kr0) * M_ + off0);     \
        cpasync16(As_ + kr1 * 128 + off1, Abase + (kb + kr1) * M_ + off1);     \
        cpasync16(Bs_ + kr0 * 128 + off0, Bbase + (kb + kr0) * G_ + off0);     \
        cpasync16(Bs_ + kr1 * 128 + off1, Bbase + (kb + kr1) * G_ + off1);     \
        asm volatile("cp.async.commit_group;");                                \
    } while (0)

    G3_ISSUE(0, 0);
    G3_ISSUE(1, 1);
    G3_ISSUE(2, 2);

    int col0 = bn * 128 + tx * 8;
    float bsum[8];
#pragma unroll
    for (int j = 0; j < 8; j++) bsum[j] = bih[col0 + j] + bhh[col0 + j];

#pragma unroll 1
    for (int kt = 0; kt < 64; kt++) {
        if (kt < 62)       asm volatile("cp.async.wait_group 2;" ::: "memory");
        else if (kt == 62) asm volatile("cp.async.wait_group 1;" ::: "memory");
        else               asm volatile("cp.async.wait_group 0;" ::: "memory");
        __syncthreads();
        if (kt + 3 < 64) G3_ISSUE(kt + 3, (kt + 3) & 3);

        const float* As_ = g3 + (kt & 3) * G3_STAGE_F;
        const float* Bs_ = As_ + 2048;
#pragma unroll
        for (int k = 0; k < 16; k++) {
            float4 av0 = *(const float4*)(As_ + k * 128 + ty * 8);
            float4 av1 = *(const float4*)(As_ + k * 128 + ty * 8 + 4);
            const ulonglong2* bp2 = (const ulonglong2*)(Bs_ + k * 128 + tx * 8);
            ulonglong2 bA = bp2[0], bB = bp2[1];
            float a_[8] = {av0.x, av0.y, av0.z, av0.w, av1.x, av1.y, av1.z, av1.w};
#pragma unroll
            for (int i = 0; i < 8; i++) {
                u64 ad = pack_dup(a_[i]);
                fma2(acc[i][0], ad, bA.x);
                fma2(acc[i][1], ad, bA.y);
                fma2(acc[i][2], ad, bB.x);
                fma2(acc[i][3], ad, bB.y);
            }
        }
    }
    #undef G3_ISSUE

    int row0 = bm * 128 + ty * 8;
#pragma unroll
    for (int i = 0; i < 8; i++) {
#pragma unroll
        for (int jp = 0; jp < 4; jp++) {
            float2 v = unpack2(acc[i][jp]);
            GI[(size_t)(row0 + i) * G_ + col0 + jp * 2]     = v.x + bsum[jp * 2];
            GI[(size_t)(row0 + i) * G_ + col0 + jp * 2 + 1] = v.y + bsum[jp * 2 + 1];
        }
    }
}

// ---------------- 4x4 register-tile inner kernel (round-13, stride 24) ------
struct Ops {
    ulonglong2 w0, w1, w2, w3;
    ulonglong2 h0, h1, h2, h3;
};
__device__ __forceinline__ void load_ops(Ops &o, const float* wp, const float* hp) {
    o.w0 = *(const ulonglong2*)(wp + 0);
    o.w1 = *(const ulonglong2*)(wp + 32);
    o.w2 = *(const ulonglong2*)(wp + 64);
    o.w3 = *(const ulonglong2*)(wp + 96);
    o.h0 = *(const ulonglong2*)(hp + 0 * 24);
    o.h1 = *(const ulonglong2*)(hp + 4 * 24);
    o.h2 = *(const ulonglong2*)(hp + 8 * 24);
    o.h3 = *(const ulonglong2*)(hp + 12 * 24);
}
__device__ __forceinline__ void do_fma(u64 (&acc)[4][4], const Ops &o) {
    fma2(acc[0][0], o.w0.x, o.h0.x); fma2(acc[0][0], o.w0.y, o.h0.y);
    fma2(acc[1][0], o.w1.x, o.h0.x); fma2(acc[1][0], o.w1.y, o.h0.y);
    fma2(acc[2][0], o.w2.x, o.h0.x); fma2(acc[2][0], o.w2.y, o.h0.y);
    fma2(acc[3][0], o.w3.x, o.h0.x); fma2(acc[3][0], o.w3.y, o.h0.y);
    fma2(acc[0][1], o.w0.x, o.h1.x); fma2(acc[0][1], o.w0.y, o.h1.y);
    fma2(acc[1][1], o.w1.x, o.h1.x); fma2(acc[1][1], o.w1.y, o.h1.y);
    fma2(acc[2][1], o.w2.x, o.h1.x); fma2(acc[2][1], o.w2.y, o.h1.y);
    fma2(acc[3][1], o.w3.x, o.h1.x); fma2(acc[3][1], o.w3.y, o.h1.y);
    fma2(acc[0][2], o.w0.x, o.h2.x); fma2(acc[0][2], o.w0.y, o.h2.y);
    fma2(acc[1][2], o.w1.x, o.h2.x); fma2(acc[1][2], o.w1.y, o.h2.y);
    fma2(acc[2][2], o.w2.x, o.h2.x); fma2(acc[2][2], o.w2.y, o.h2.y);
    fma2(acc[3][2], o.w3.x, o.h2.x); fma2(acc[3][2], o.w3.y, o.h2.y);
    fma2(acc[0][3], o.w0.x, o.h3.x); fma2(acc[0][3], o.w0.y, o.h3.y);
    fma2(acc[1][3], o.w1.x, o.h3.x); fma2(acc[1][3], o.w1.y, o.h3.y);
    fma2(acc[2][3], o.w2.x, o.h3.x); fma2(acc[2][3], o.w2.y, o.h3.y);
    fma2(acc[3][3], o.w3.x, o.h3.x); fma2(acc[3][3], o.w3.y, o.h3.y);
}

// ============================================================================
// Persistent recurrent layer — EXACT round-13 winner (2-stage h pipeline,
// 16k chunks, stride 24). Only change: the y0T scatter-store (consumed only by
// the NEXT kernel, stream-ordered) moved after the flag publish so it is off
// the producer->flag release chain that gates consumers' step start.
// ============================================================================
#define WSM_F   (256 * 32 * 4)
#define HSTG_F  (16 * 24)
#define HBUF_F  (16 * 2 * HSTG_F)
#define CMB_F   (4 * 64 * 36)
#define SMEM_STEP ((WSM_F + HBUF_F + CMB_F) * 4)

__global__ __launch_bounds__(512, 1) void lstm_layer(
    int layer, const float* __restrict__ whh,
    float* __restrict__ y1, float* __restrict__ hn_base, float* __restrict__ cn_base)
{
    extern __shared__ float sm[];
    float* Wsm  = sm;
    float* Hbuf = sm + WSM_F;
    float* Cmb  = sm + WSM_F + HBUF_F;

    const size_t BH = (size_t)B_ * H_;
    int tid  = threadIdx.x;
    int lane = tid & 31;
    int wy   = tid >> 5;
    int ks   = wy & 3;
    int wb0  = (wy >> 2) * 16;
    int lx   = lane & 3;
    int ly   = lane >> 2;
    int jb   = blockIdx.x * 8;

    float* hbase_ = (layer == 0) ? g_y0 : y1;

    {
        int c = tid & 31;
        int wn = ((c >> 3) * H_) + jb + (c & 7);
        const float* wrow = whh + (size_t)wn * H_;
        int dstbase = (c & 3) * 32 + (c >> 2) * 4;
        int k4b = tid >> 5;
#pragma unroll
        for (int q = 0; q < 16; q++) {
            int k4 = k4b + q * 16;
            float4 v = *(const float4*)(wrow + k4 * 4);
            *(float4*)&Wsm[k4 * 128 + dstbase] = v;
        }
    }
    if (tid == 0) ((volatile int*)g_flag)[blockIdx.x] = 0;
    gsync();

    float* hwbuf = Hbuf + wy * (2 * HSTG_F);
    int n_base = ((ly >> 1) * H_) + jb + ((ly & 1) * 4);
    int cb = tid >> 3, cj = tid & 7;
    float cst = 0.0f;
    const volatile int* myflag = (volatile int*)&g_flag[ks * 32 + lane];

    for (int t = 0; t < S_; t++) {
        const float* gi_t = g_gi + (size_t)t * B_ * G_;
        float4 gi4[4];
        if (ks == 0) {
#pragma unroll
            for (int rr = 0; rr < 4; rr++)
                gi4[rr] = *(const float4*)(gi_t + (size_t)(wb0 + lx + 4 * rr) * G_ + n_base);
        }

        u64 acc[4][4];
#pragma unroll
        for (int cc = 0; cc < 4; cc++)
#pragma unroll
            for (int rr = 0; rr < 4; rr++) acc[cc][rr] = 0ull;

        if (t > 0) {
            for (;;) {
                int v = *myflag;
                if (__all_sync(0xffffffffu, v >= t)) break;
                __nanosleep(64);
            }
            __threadfence();

            const float* hsrc = hbase_ + (size_t)(t - 1) * BH;
            const float* hk = hsrc + ks * 256;

#pragma unroll
            for (int q = 0; q < 2; q++) {
                int li = lane + 32 * q;
                int rowb = li & 15, kq = li >> 4;
                cpasync16(hwbuf + rowb * 24 + kq * 4,
                          hk + (size_t)(wb0 + rowb) * H_ + kq * 4);
            }
            asm volatile("cp.async.commit_group;");

            for (int ch = 0; ch < 16; ch++) {
                if (ch < 15) {
                    float* dst = hwbuf + ((ch + 1) & 1) * HSTG_F;
                    const float* src = hk + (ch + 1) * 16;
#pragma unroll
                    for (int q = 0; q < 2; q++) {
                        int li = lane + 32 * q;
                        int rowb = li & 15, kq = li >> 4;
                        cpasync16(dst + rowb * 24 + kq * 4,
                                  src + (size_t)(wb0 + rowb) * H_ + kq * 4);
                    }
                    asm volatile("cp.async.commit_group;");
                    asm volatile("cp.async.wait_group 1;");
                } else {
                    asm volatile("cp.async.wait_group 0;");
                }
                __syncwarp();

                const float* hs = hwbuf + (ch & 1) * HSTG_F;
                int k4g0 = ks * 64 + ch * 4;
                const float* wbase = Wsm + (size_t)k4g0 * 128 + ly * 4;
                const float* hb = hs + lx * 24;

                Ops ops0, ops1;
                load_ops(ops0, wbase, hb);
                load_ops(ops1, wbase + 128, hb + 4);
                do_fma(acc, ops0);
                load_ops(ops0, wbase + 256, hb + 8);
                do_fma(acc, ops1);
                load_ops(ops1, wbase + 384, hb + 12);
                do_fma(acc, ops0);
                do_fma(acc, ops1);

                __syncwarp();
            }
        }

#pragma unroll
        for (int rr = 0; rr < 4; rr++) {
            float4 v;
            v.x = hsum2(acc[0][rr]);
            v.y = hsum2(acc[1][rr]);
            v.z = hsum2(acc[2][rr]);
            v.w = hsum2(acc[3][rr]);
            if (ks == 0) {
                v.x += gi4[rr].x; v.y += gi4[rr].y;
                v.z += gi4[rr].z; v.w += gi4[rr].w;
            }
            int b = wb0 + lx + 4 * rr;
            *(float4*)&Cmb[(ks * 64 + b) * 36 + ly * 4] = v;
        }
        __syncthreads();

        float z[4];
#pragma unroll
        for (int g = 0; g < 4; g++) {
            int c = g * 8 + cj;
            z[g] = Cmb[(0 * 64 + cb) * 36 + c]
                 + Cmb[(1 * 64 + cb) * 36 + c]
                 + Cmb[(2 * 64 + cb) * 36 + c]
                 + Cmb[(3 * 64 + cb) * 36 + c];
        }
        cst = sigf(z[1]) * cst + sigf(z[0]) * tanhf_(z[2]);
        float hv = sigf(z[3]) * tanhf_(cst);

        size_t hoff = (size_t)cb * H_ + jb + cj;
        (hbase_ + (size_t)t * BH)[hoff] = hv;
        if (t == S_ - 1) {
            size_t o = (size_t)layer * BH + hoff;
            hn_base[o] = hv;
            cn_base[o] = cst;
        }

        // h stores done -> release progress flag to consumer CTAs
        __syncthreads();
        if (tid == 0) {
            __threadfence();
            atomicExch(&g_flag[blockIdx.x], t + 1);
        }

        // y0T is consumed only by the NEXT kernel (stream-ordered): store it
        // off the release chain.
        if (layer == 0)
            g_y0T[(size_t)(jb + cj) * M_ + t * 64 + cb] = hv;

        __syncthreads();
    }
}

// ============================================================================
// kernel_launch: 7 graph nodes.
// Output layout: y1 [S,B,H] | h_n [2,B,H] | c_n [2,B,H]
// ============================================================================
extern "C" void kernel_launch(void* const* d_in, const int* in_sizes, int n_in,
                              void* d_out, int out_size)
{
    const float* x     = (const float*)d_in[0];
    const float* w_ih0 = (const float*)d_in[1];
    const float* w_hh0 = (const float*)d_in[2];
    const float* b_ih0 = (const float*)d_in[3];
    const float* b_hh0 = (const float*)d_in[4];
    const float* w_ih1 = (const float*)d_in[5];
    const float* w_hh1 = (const float*)d_in[6];
    const float* b_ih1 = (const float*)d_in[7];
    const float* b_hh1 = (const float*)d_in[8];

    float* y1 = (float*)d_out;
    float* hn = y1 + (size_t)S_ * B_ * H_;
    float* cn = hn + 2 * (size_t)B_ * H_;

    cudaFuncSetAttribute(lstm_layer, cudaFuncAttributeMaxDynamicSharedMemorySize, SMEM_STEP);
    cudaFuncSetAttribute(gemm3, cudaFuncAttributeMaxDynamicSharedMemorySize, G3_SMEM);

    float* xT  = nullptr; cudaGetSymbolAddress((void**)&xT,  g_xT);
    float* wT  = nullptr; cudaGetSymbolAddress((void**)&wT,  g_wT);

    dim3 tb(32, 8);
    transp<<<dim3(H_ / 32, M_ / 32), tb>>>(x, xT, M_, H_);
    transp<<<dim3(H_ / 32, G_ / 32), tb>>>(w_ih0, wT, G_, H_);
    transp<<<dim3(H_ / 32, G_ / 32), tb>>>(w_ih1, wT + (size_t)H_ * G_, G_, H_);

    dim3 ggrid(G_ / 128, M_ / 128);  // (32, 256)

    gemm3<<<ggrid, 256, G3_SMEM>>>(0, b_ih0, b_hh0);
    lstm_layer<<<NCTA_, 512, SMEM_STEP>>>(0, w_hh0, y1, hn, cn);
    gemm3<<<ggrid, 256, G3_SMEM>>>(1, b_ih1, b_hh1);
    lstm_layer<<<NCTA_, 512, SMEM_STEP>>>(1, w_hh1, y1, hn, cn);
}